// round 1
// baseline (speedup 1.0000x reference)
#include <cuda_runtime.h>

// Trilinear resample of (B=4, D=64, H=64, W=64, C=32) fp32 volume with
// identity affine theta. Per reference: coord_i = 0.5*(linspace(-1,1,N)[i]+1)*(N-2)
//   = (N-2)*i/(N-1), so coords span [0, N-2]; x1=x0+1 <= N-1, no clamping needed.
//
// One thread computes one float4 (4 channels) of one output voxel:
//   8 threads per voxel (C=32), gathers 8 corner float4s, weighted sum.

#define B_ 4
#define D_ 64
#define H_ 64
#define W_ 64
#define C_ 32
#define C4_ (C_ / 4)   // 8 float4 per voxel

__global__ __launch_bounds__(256) void trilerp_kernel(
    const float4* __restrict__ in, float4* __restrict__ out)
{
    const int idx = blockIdx.x * blockDim.x + threadIdx.x;
    // total float4s = B*D*H*W*C4 = 4*64*64*64*8 = 8388608 (exact multiple of grid)
    const int c4 = idx & (C4_ - 1);
    const int w  = (idx >> 3)  & (W_ - 1);
    const int h  = (idx >> 9)  & (H_ - 1);
    const int d  = (idx >> 15) & (D_ - 1);
    const int b  = idx >> 21;

    // Match reference: xs = linspace(-1,1,N)[i]; f = 0.5*(xs+1)*(N-2)
    const float gx = -1.0f + (float)w * (2.0f / (float)(W_ - 1));
    const float gy = -1.0f + (float)h * (2.0f / (float)(H_ - 1));
    const float gz = -1.0f + (float)d * (2.0f / (float)(D_ - 1));
    float fx = 0.5f * (gx + 1.0f) * (float)(W_ - 2);
    float fy = 0.5f * (gy + 1.0f) * (float)(H_ - 2);
    float fz = 0.5f * (gz + 1.0f) * (float)(D_ - 2);

    int x0 = (int)floorf(fx);
    int y0 = (int)floorf(fy);
    int z0 = (int)floorf(fz);
    // safety clamps (coords should already be in [0, N-2])
    x0 = max(0, min(x0, W_ - 2));
    y0 = max(0, min(y0, H_ - 2));
    z0 = max(0, min(z0, D_ - 2));

    const float tx = fx - (float)x0;
    const float ty = fy - (float)y0;
    const float tz = fz - (float)z0;
    const float sx = 1.0f - tx;
    const float sy = 1.0f - ty;
    const float sz = 1.0f - tz;

    // weights: w_zyx, corner (x0+x, y0+y, z0+z)
    const float w000 = sx * sy * sz;
    const float w001 = tx * sy * sz;  // x1
    const float w010 = sx * ty * sz;  // y1
    const float w011 = tx * ty * sz;
    const float w100 = sx * sy * tz;  // z1
    const float w101 = tx * sy * tz;
    const float w110 = sx * ty * tz;
    const float w111 = tx * ty * tz;

    // float4 strides
    const long sxl = C4_;            // +1 in x
    const long syl = (long)W_ * C4_; // +1 in y
    const long szl = (long)H_ * W_ * C4_;

    const long base = ((((long)b * D_ + z0) * H_ + y0) * W_ + x0) * C4_ + c4;

    const float4 v000 = __ldg(in + base);
    const float4 v001 = __ldg(in + base + sxl);
    const float4 v010 = __ldg(in + base + syl);
    const float4 v011 = __ldg(in + base + syl + sxl);
    const float4 v100 = __ldg(in + base + szl);
    const float4 v101 = __ldg(in + base + szl + sxl);
    const float4 v110 = __ldg(in + base + szl + syl);
    const float4 v111 = __ldg(in + base + szl + syl + sxl);

    float4 r;
    r.x = w000 * v000.x;
    r.y = w000 * v000.y;
    r.z = w000 * v000.z;
    r.w = w000 * v000.w;
    r.x = fmaf(w001, v001.x, r.x); r.y = fmaf(w001, v001.y, r.y);
    r.z = fmaf(w001, v001.z, r.z); r.w = fmaf(w001, v001.w, r.w);
    r.x = fmaf(w010, v010.x, r.x); r.y = fmaf(w010, v010.y, r.y);
    r.z = fmaf(w010, v010.z, r.z); r.w = fmaf(w010, v010.w, r.w);
    r.x = fmaf(w011, v011.x, r.x); r.y = fmaf(w011, v011.y, r.y);
    r.z = fmaf(w011, v011.z, r.z); r.w = fmaf(w011, v011.w, r.w);
    r.x = fmaf(w100, v100.x, r.x); r.y = fmaf(w100, v100.y, r.y);
    r.z = fmaf(w100, v100.z, r.z); r.w = fmaf(w100, v100.w, r.w);
    r.x = fmaf(w101, v101.x, r.x); r.y = fmaf(w101, v101.y, r.y);
    r.z = fmaf(w101, v101.z, r.z); r.w = fmaf(w101, v101.w, r.w);
    r.x = fmaf(w110, v110.x, r.x); r.y = fmaf(w110, v110.y, r.y);
    r.z = fmaf(w110, v110.z, r.z); r.w = fmaf(w110, v110.w, r.w);
    r.x = fmaf(w111, v111.x, r.x); r.y = fmaf(w111, v111.y, r.y);
    r.z = fmaf(w111, v111.z, r.z); r.w = fmaf(w111, v111.w, r.w);

    out[idx] = r;
}

extern "C" void kernel_launch(void* const* d_in, const int* in_sizes, int n_in,
                              void* d_out, int out_size)
{
    const float4* in = (const float4*)d_in[0];
    float4* out = (float4*)d_out;
    const int total4 = B_ * D_ * H_ * W_ * C4_;  // 8388608
    const int threads = 256;
    const int blocks = total4 / threads;         // 32768
    trilerp_kernel<<<blocks, threads>>>(in, out);
}